// round 7
// baseline (speedup 1.0000x reference)
#include <cuda_runtime.h>

// 8192x8192 fp32 input; 10 3x3 SAME convs; 4 2x2 maxpools.
// Stages A,B: [conv,conv,pool]  (new wide kernel, K=2)
// Stages C,D: [conv,conv,conv,pool] (proven kernel, K=3, + prefetch ring)

__device__ float g_buf0[4096u * 4096u];
__device__ float g_buf1[2048u * 2048u];
__device__ float g_buf2[1024u * 1024u];

// Load 8 consecutive floats (two aligned float4) from smem.
__device__ __forceinline__ void ld8(float* d, const float* p) {
    float4 a = *(const float4*)(p);
    float4 b = *(const float4*)(p + 4);
    d[0] = a.x; d[1] = a.y; d[2] = a.z; d[3] = a.w;
    d[4] = b.x; d[5] = b.y; d[6] = b.z; d[7] = b.w;
}

__device__ __forceinline__ void conv_row(float v[4], const float* r0,
                                         const float* r1, const float* r2,
                                         const float k[9]) {
#pragma unroll
    for (int q = 0; q < 4; ++q) {
        v[q] = r0[q] * k[0] + r0[q + 1] * k[1] + r0[q + 2] * k[2]
             + r1[q] * k[3] + r1[q + 1] * k[4] + r1[q + 2] * k[5]
             + r2[q] * k[6] + r2[q + 1] * k[7] + r2[q + 2] * k[8];
    }
}

// ===================== K=2 kernel (stages A, B) =====================
// Block -> 32x32 pooled tile. Buffer 74 rows x 72 cols. Threads: 17 strips
// (4 cols) x 12 groups (6 rows) = 204 active of 224. Shifted-origin layers:
// dst[r][x] = conv(src)[r+1][x+1], so every layer reads/writes col 4s aligned.
#define CS 72
#define RS 74
#define WNT 224

template <bool EDGE>
__device__ __forceinline__ void wlayer_mid(const float* __restrict__ src,
                                           float* __restrict__ dst,
                                           const float k[9], int s, int g,
                                           int ey0, int ex0, unsigned uw) {
    const float* sp = src + (6 * g) * CS + 4 * s;
    float r[4][8];
    ld8(r[0], sp); ld8(r[1], sp + CS); ld8(r[2], sp + 2 * CS);
#pragma unroll
    for (int j = 0; j < 6; ++j) {
        if (j < 5) ld8(r[(j + 3) & 3], sp + (j + 3) * CS);  // prefetch
        float v[4];
        conv_row(v, r[j & 3], r[(j + 1) & 3], r[(j + 2) & 3], k);
        if (EDGE) {  // SAME zero-pad at image boundary, re-applied per layer
            const bool rok = (unsigned)(ey0 + 6 * g + j) < uw;
#pragma unroll
            for (int q = 0; q < 4; ++q)
                if (!(rok && ((unsigned)(ex0 + 4 * s + q) < uw))) v[q] = 0.0f;
        }
        *(float4*)(dst + (6 * g + j) * CS + 4 * s) =
            make_float4(v[0], v[1], v[2], v[3]);
    }
}

// Last conv fused with 2x2 maxpool (interior blocks; s<16, g<11).
__device__ __forceinline__ void wlayer_pool(const float* __restrict__ src,
                                            float* __restrict__ out, int outW,
                                            const float k[9], int s, int g,
                                            int oy, int ox) {
    const float* sp = src + (6 * g) * CS + 4 * s;
    float r[4][8];
    ld8(r[0], sp); ld8(r[1], sp + CS); ld8(r[2], sp + 2 * CS);
    float p0, p1;
#pragma unroll
    for (int j = 0; j < 6; ++j) {
        if (j < 5) ld8(r[(j + 3) & 3], sp + (j + 3) * CS);
        float v[4];
        conv_row(v, r[j & 3], r[(j + 1) & 3], r[(j + 2) & 3], k);
        float m0 = fmaxf(v[0], v[1]);
        float m1 = fmaxf(v[2], v[3]);
        if ((j & 1) == 0) { p0 = m0; p1 = m1; }
        else {
            int prow = 3 * g + (j >> 1);
            if (prow < 32)
                *(float2*)(out + (long)(oy + prow) * outW + ox + 2 * s) =
                    make_float2(fmaxf(p0, m0), fmaxf(p1, m1));
        }
    }
}

__global__ __launch_bounds__(WNT, 4)
void stage2_kernel(const float* __restrict__ in, int inW,
                   float* __restrict__ out, int outW,
                   const float* __restrict__ w0,
                   const float* __restrict__ w1) {
    constexpr int EXT = 68;
    __shared__ float bufA[RS * CS];
    __shared__ float bufB[RS * CS];
    __shared__ float wts[18];

    const int tid = threadIdx.x;
    if (tid < 18) wts[tid] = (tid < 9) ? w0[tid] : w1[tid - 9];

    const int gx0 = blockIdx.x * 64 - 2;
    const int gy0 = blockIdx.y * 64 - 2;
    const unsigned uw = (unsigned)inW;  // square image
    const bool edge = (gx0 < 0) || (gy0 < 0) ||
                      (gx0 + EXT > inW) || (gy0 + EXT > inW);

    if (!edge) {
        // Interior: load full 74x72 window unconditionally (valid halo data;
        // interior guarantees gx0+CS, gy0+RS within image). Aligned float2.
        if (tid < 216) {
            const int tc = tid % 36;  // float2 column
            const int tr = tid / 36;  // 6 concurrent rows
            const float* gp = in + (long)(gy0 + tr) * inW + gx0 + 2 * tc;
            float* bp = bufA + tr * CS + 2 * tc;
#pragma unroll
            for (int r = tr; r < RS; r += 6, gp += 6L * inW, bp += 6 * CS)
                *(float2*)bp = *(const float2*)gp;
        }
    } else {
        // Edge: zero-init both buffers, masked scalar load.
        for (int i = tid; i < RS * CS; i += WNT) {
            int r = i / CS, c = i - r * CS;
            float v = 0.0f;
            if (r < EXT && c < EXT) {
                int gy = gy0 + r, gx = gx0 + c;
                if ((unsigned)gy < uw && (unsigned)gx < uw)
                    v = in[(long)gy * inW + gx];
            }
            bufA[i] = v;
            bufB[i] = 0.0f;
        }
    }
    __syncthreads();

    const bool active = tid < 204;
    const int s = tid % 17;
    const int g = tid / 17;
    const int ox = blockIdx.x * 32, oy = blockIdx.y * 32;

    float k[9];
    if (!edge) {
        if (active) {
#pragma unroll
            for (int m = 0; m < 9; ++m) k[m] = wts[m];
            wlayer_mid<false>(bufA, bufB, k, s, g, 0, 0, uw);
        }
        __syncthreads();
        if (active && s < 16 && g < 11) {
#pragma unroll
            for (int m = 0; m < 9; ++m) k[m] = wts[9 + m];
            wlayer_pool(bufB, out, outW, k, s, g, oy, ox);
        }
    } else {
        if (active) {
#pragma unroll
            for (int m = 0; m < 9; ++m) k[m] = wts[m];
            wlayer_mid<true>(bufA, bufB, k, s, g, gy0 + 1, gx0 + 1, uw);
        }
        __syncthreads();
        if (active) {
#pragma unroll
            for (int m = 0; m < 9; ++m) k[m] = wts[9 + m];
            wlayer_mid<true>(bufB, bufA, k, s, g, gy0 + 2, gx0 + 2, uw);
        }
        __syncthreads();
        // Pool over bufA [0,64)^2 (buf coord 0 == abs blockIdx*64).
        for (int i = tid; i < 1024; i += WNT) {
            int py = i >> 5, px = i & 31;
            const float* p = bufA + (2 * py) * CS + 2 * px;
            float m = fmaxf(fmaxf(p[0], p[1]), fmaxf(p[CS], p[CS + 1]));
            out[(long)(oy + py) * outW + ox + px] = m;
        }
    }
}

// ===================== K=3 kernel (stages C, D) =====================
#define NT 320
#define BD 72
#define STRIPS 17
#define NACT (STRIPS * STRIPS)

template <bool EDGE>
__device__ __forceinline__ void layer_mid(const float* __restrict__ src,
                                          float* __restrict__ dst,
                                          const float k[9], int s, int g,
                                          int ey0, int ex0, unsigned uw) {
    const float* sp = src + (4 * g) * BD + 4 * s;
    float r[4][8];
    ld8(r[0], sp); ld8(r[1], sp + BD); ld8(r[2], sp + 2 * BD);
#pragma unroll
    for (int j = 0; j < 4; ++j) {
        if (j < 3) ld8(r[(j + 3) & 3], sp + (j + 3) * BD);  // prefetch
        float v[4];
        conv_row(v, r[j & 3], r[(j + 1) & 3], r[(j + 2) & 3], k);
        if (EDGE) {
            const bool rok = (unsigned)(ey0 + 4 * g + j) < uw;
#pragma unroll
            for (int q = 0; q < 4; ++q)
                if (!(rok && ((unsigned)(ex0 + 4 * s + q) < uw))) v[q] = 0.0f;
        }
        *(float4*)(dst + (4 * g + j) * BD + 4 * s) =
            make_float4(v[0], v[1], v[2], v[3]);
    }
}

__device__ __forceinline__ void layer_last_pool(const float* __restrict__ src,
                                                float* __restrict__ out,
                                                int outW, const float k[9],
                                                int s, int g, int oy, int ox) {
    const float* sp = src + (4 * g) * BD + 4 * s;
    float r[4][8];
    ld8(r[0], sp); ld8(r[1], sp + BD); ld8(r[2], sp + 2 * BD);
    float p[2][2];
#pragma unroll
    for (int j = 0; j < 4; ++j) {
        if (j < 3) ld8(r[(j + 3) & 3], sp + (j + 3) * BD);
        float v[4];
        conv_row(v, r[j & 3], r[(j + 1) & 3], r[(j + 2) & 3], k);
        const int pr = j >> 1;
        float m0 = fmaxf(v[0], v[1]);
        float m1 = fmaxf(v[2], v[3]);
        if ((j & 1) == 0) { p[pr][0] = m0; p[pr][1] = m1; }
        else             { p[pr][0] = fmaxf(p[pr][0], m0);
                           p[pr][1] = fmaxf(p[pr][1], m1); }
    }
    float* op = out + (long)(oy + 2 * g) * outW + (ox + 2 * s);
    *(float2*)op = make_float2(p[0][0], p[0][1]);
    *(float2*)(op + outW) = make_float2(p[1][0], p[1][1]);
}

__global__ __launch_bounds__(NT, 4)
void stage3_kernel(const float* __restrict__ in, int inW,
                   float* __restrict__ out, int outW,
                   const float* __restrict__ w0,
                   const float* __restrict__ w1,
                   const float* __restrict__ w2) {
    constexpr int K = 3, EXT = 70;
    __shared__ float bufA[BD * BD];
    __shared__ float bufB[BD * BD];
    __shared__ float wts[27];

    const int tid = threadIdx.x;
    if (tid < 27) {
        const float* wp = (tid < 9) ? w0 : ((tid < 18) ? w1 : w2);
        wts[tid] = wp[tid % 9];
    }

    const int gx0 = blockIdx.x * 64 - K;
    const int gy0 = blockIdx.y * 64 - K;
    const unsigned uw = (unsigned)inW;
    const bool edge = (gx0 < 0) || (gy0 < 0) ||
                      (gx0 + EXT > inW) || (gy0 + EXT > inW);

    // Zero bufB rim (finite garbage in halo never reaches valid outputs).
    for (int i = tid; i < BD * BD / 4; i += NT)
        ((float4*)bufB)[i] = make_float4(0.f, 0.f, 0.f, 0.f);

    for (int i = tid; i < BD * BD; i += NT) {
        int r = i / BD, c = i - r * BD;
        float v = 0.0f;
        if (r < EXT && c < EXT) {
            int gy = gy0 + r, gx = gx0 + c;
            if (!edge || ((unsigned)gy < uw && (unsigned)gx < uw))
                v = in[(long)gy * inW + gx];
        }
        bufA[i] = v;
    }
    __syncthreads();

    const bool active = tid < NACT;
    const int s = tid % STRIPS;
    const int g = tid / STRIPS;
    const int ox = blockIdx.x * 32, oy = blockIdx.y * 32;

    float k[9];
    float* src = bufA;
    float* dst = bufB;

#pragma unroll
    for (int c = 0; c < K - 1; ++c) {
        if (active) {
#pragma unroll
            for (int m = 0; m < 9; ++m) k[m] = wts[c * 9 + m];
            if (edge) layer_mid<true >(src, dst, k, s, g,
                                       gy0 + c + 1, gx0 + c + 1, uw);
            else      layer_mid<false>(src, dst, k, s, g, 0, 0, uw);
        }
        __syncthreads();
        float* t = src; src = dst; dst = t;
    }

    if (!edge) {
        if (s < 16 && g < 16 && active) {
#pragma unroll
            for (int m = 0; m < 9; ++m) k[m] = wts[(K - 1) * 9 + m];
            layer_last_pool(src, out, outW, k, s, g, oy, ox);
        }
    } else {
        if (active) {
#pragma unroll
            for (int m = 0; m < 9; ++m) k[m] = wts[(K - 1) * 9 + m];
            layer_mid<true>(src, dst, k, s, g, gy0 + K, gx0 + K, uw);
        }
        __syncthreads();
        for (int i = tid; i < 1024; i += NT) {
            int py = i >> 5, px = i & 31;
            const float* p = dst + (2 * py) * BD + 2 * px;
            float m = fmaxf(fmaxf(p[0], p[1]), fmaxf(p[BD], p[BD + 1]));
            out[(long)(oy + py) * outW + ox + px] = m;
        }
    }
}

extern "C" void kernel_launch(void* const* d_in, const int* in_sizes, int n_in,
                              void* d_out, int out_size) {
    const float* x = (const float*)d_in[0];
    const float* w[10];
    for (int i = 0; i < 10; ++i) w[i] = (const float*)d_in[1 + i];

    float *b0, *b1, *b2;
    cudaGetSymbolAddress((void**)&b0, g_buf0);
    cudaGetSymbolAddress((void**)&b1, g_buf1);
    cudaGetSymbolAddress((void**)&b2, g_buf2);

    float* outp = (float*)d_out;

    stage2_kernel<<<dim3(128, 128), WNT>>>(x,  8192, b0,  4096, w[0], w[1]);
    stage2_kernel<<<dim3(64, 64),   WNT>>>(b0, 4096, b1,  2048, w[2], w[3]);
    stage3_kernel<<<dim3(32, 32),   NT>>>(b1, 2048, b2,  1024, w[4], w[5], w[6]);
    stage3_kernel<<<dim3(16, 16),   NT>>>(b2, 1024, outp, 512, w[7], w[8], w[9]);
}

// round 8
// speedup vs baseline: 1.1557x; 1.1557x over previous
#include <cuda_runtime.h>

// 8192x8192 fp32 input; 10 3x3 SAME convs; 4 2x2 maxpools.
// Stages: [conv,conv,pool] x2 then [conv,conv,conv,pool] x2.
// R8 = R5 proven kernel + interior blocks skip zero-init and load masks.

__device__ float g_buf0[4096u * 4096u];
__device__ float g_buf1[2048u * 2048u];
__device__ float g_buf2[1024u * 1024u];

#define NT 320                 // threads per block (10 warps)
#define BD 72                  // smem buffer dim (stride), 16B-aligned rows
#define STRIPS 17              // 17 x 17 threads x (4x4 px) cover 68x68
#define NACT (STRIPS * STRIPS) // 289 active conv threads

// Load 8 consecutive floats (two aligned float4) from smem.
__device__ __forceinline__ void ld8(float* d, const float* p) {
    float4 a = *(const float4*)(p);
    float4 b = *(const float4*)(p + 4);
    d[0] = a.x; d[1] = a.y; d[2] = a.z; d[3] = a.w;
    d[4] = b.x; d[5] = b.y; d[6] = b.z; d[7] = b.w;
}

__device__ __forceinline__ void conv_row(float v[4], const float* r0,
                                         const float* r1, const float* r2,
                                         const float k[9]) {
#pragma unroll
    for (int q = 0; q < 4; ++q) {
        v[q] = r0[q] * k[0] + r0[q + 1] * k[1] + r0[q + 2] * k[2]
             + r1[q] * k[3] + r1[q + 1] * k[4] + r1[q + 2] * k[5]
             + r2[q] * k[6] + r2[q + 1] * k[7] + r2[q + 2] * k[8];
    }
}

// One conv layer, shifted-origin: dst[r][x] = conv(src)[r+1][x+1].
// Reads ld8 at col 4s (window offset 0), stores aligned float4 at col 4s.
template <bool EDGE>
__device__ __forceinline__ void layer_mid(const float* __restrict__ src,
                                          float* __restrict__ dst,
                                          const float k[9], int s, int g,
                                          int ey0, int ex0, unsigned uw) {
    const float* sp = src + (4 * g) * BD + 4 * s;
    float r[3][8];
    ld8(r[0], sp);
    ld8(r[1], sp + BD);
#pragma unroll
    for (int j = 0; j < 4; ++j) {
        ld8(r[(j + 2) % 3], sp + (2 + j) * BD);
        float v[4];
        conv_row(v, r[j % 3], r[(j + 1) % 3], r[(j + 2) % 3], k);
        if (EDGE) {  // SAME zero-pad at the image boundary, per layer
            const bool rok = (unsigned)(ey0 + 4 * g + j) < uw;
#pragma unroll
            for (int q = 0; q < 4; ++q)
                if (!(rok && ((unsigned)(ex0 + 4 * s + q) < uw))) v[q] = 0.0f;
        }
        *(float4*)(dst + (4 * g + j) * BD + 4 * s) =
            make_float4(v[0], v[1], v[2], v[3]);
    }
}

// Last conv layer fused with 2x2 maxpool (interior blocks; s,g < 16).
__device__ __forceinline__ void layer_last_pool(const float* __restrict__ src,
                                                float* __restrict__ out,
                                                int outW, const float k[9],
                                                int s, int g, int oy, int ox) {
    const float* sp = src + (4 * g) * BD + 4 * s;
    float r[3][8];
    ld8(r[0], sp);
    ld8(r[1], sp + BD);
    float p[2][2];
#pragma unroll
    for (int j = 0; j < 4; ++j) {
        ld8(r[(j + 2) % 3], sp + (2 + j) * BD);
        float v[4];
        conv_row(v, r[j % 3], r[(j + 1) % 3], r[(j + 2) % 3], k);
        const int pr = j >> 1;
        float m0 = fmaxf(v[0], v[1]);
        float m1 = fmaxf(v[2], v[3]);
        if ((j & 1) == 0) { p[pr][0] = m0; p[pr][1] = m1; }
        else             { p[pr][0] = fmaxf(p[pr][0], m0);
                           p[pr][1] = fmaxf(p[pr][1], m1); }
    }
    float* op = out + (long)(oy + 2 * g) * outW + (ox + 2 * s);
    *(float2*)op = make_float2(p[0][0], p[0][1]);
    *(float2*)(op + outW) = make_float2(p[1][0], p[1][1]);
}

// Fused stage: K 3x3 convs (SAME at image boundary) + 2x2 maxpool.
// Block -> 32x32 pooled tile (64x64 pre-pool). EXT = 64 + 2K loaded extent.
template <int K>
__global__ __launch_bounds__(NT, 4)
void stage_kernel(const float* __restrict__ in, int inW,
                  float* __restrict__ out, int outW,
                  const float* __restrict__ w0,
                  const float* __restrict__ w1,
                  const float* __restrict__ w2) {
    constexpr int EXT = 64 + 2 * K;
    __shared__ float bufA[BD * BD];
    __shared__ float bufB[BD * BD];
    __shared__ float wts[27];

    const int tid = threadIdx.x;
    if (tid < K * 9) {
        const float* wp = (tid < 9) ? w0 : ((tid < 18) ? w1 : w2);
        wts[tid] = wp[tid % 9];
    }

    const int gx0 = blockIdx.x * 64 - K;
    const int gy0 = blockIdx.y * 64 - K;
    const unsigned uw = (unsigned)inW;  // square image
    const bool edge = (gx0 < 0) || (gy0 < 0) ||
                      (gx0 + EXT > inW) || (gy0 + EXT > inW);

    if (!edge) {
        // Interior: no zero-init needed. Validity trace: unwritten buffer
        // cells only ever feed intermediate rows/cols >= 66, which no later
        // layer tap that reaches the pooled output reads; loaded-but-unused
        // ld8 lanes are discarded in registers. Junk is finite.
        if (K == 2) {
            // gx0 even, and interior => gx0+71 <= inW-59: load the full
            // 72x72 window unconditionally with aligned float2.
            if (tid < 288) {
                const int tc = tid % 36;            // float2 column
                const int tr = tid / 36;            // 8 concurrent rows
                const float* gp = in + (long)(gy0 + tr) * inW + gx0 + 2 * tc;
                float* bp = bufA + tr * BD + 2 * tc;
#pragma unroll
                for (int r = 0; r < 9; ++r, gp += 8L * inW, bp += 8 * BD)
                    *(float2*)bp = *(const float2*)gp;
            }
        } else {
            // K=3: gx0 odd; masked to EXT (OOB otherwise), no image masks.
            for (int i = tid; i < BD * BD; i += NT) {
                int r = i / BD, c = i - r * BD;
                if (r < EXT && c < EXT)
                    bufA[i] = in[(long)(gy0 + r) * inW + (gx0 + c)];
            }
        }
    } else {
        // Edge: zero both buffers, masked scalar load (proven path).
        for (int i = tid; i < BD * BD; i += NT) {
            int r = i / BD, c = i - r * BD;
            float v = 0.0f;
            if (r < EXT && c < EXT) {
                int gy = gy0 + r, gx = gx0 + c;
                if ((unsigned)gy < uw && (unsigned)gx < uw)
                    v = in[(long)gy * inW + gx];
            }
            bufA[i] = v;
            bufB[i] = 0.0f;
        }
    }
    __syncthreads();

    const bool active = tid < NACT;
    const int s = tid % STRIPS;
    const int g = tid / STRIPS;
    const int ox = blockIdx.x * 32, oy = blockIdx.y * 32;

    float k[9];
    float* src = bufA;
    float* dst = bufB;

    // ---- layers 0 .. K-2 (to smem) ----
#pragma unroll
    for (int c = 0; c < K - 1; ++c) {
        if (active) {
#pragma unroll
            for (int m = 0; m < 9; ++m) k[m] = wts[c * 9 + m];
            if (edge) layer_mid<true >(src, dst, k, s, g,
                                       gy0 + c + 1, gx0 + c + 1, uw);
            else      layer_mid<false>(src, dst, k, s, g, 0, 0, uw);
        }
        __syncthreads();
        float* t = src; src = dst; dst = t;
    }

    // ---- last layer ----
    if (!edge) {
        if (s < 16 && g < 16 && active) {
#pragma unroll
            for (int m = 0; m < 9; ++m) k[m] = wts[(K - 1) * 9 + m];
            layer_last_pool(src, out, outW, k, s, g, oy, ox);
        }
        // no further smem use; no sync needed before exit
    } else {
        if (active) {
#pragma unroll
            for (int m = 0; m < 9; ++m) k[m] = wts[(K - 1) * 9 + m];
            layer_mid<true>(src, dst, k, s, g, gy0 + K, gx0 + K, uw);
        }
        __syncthreads();
        // Pool over dst [0,64)^2 (buf coord 0 == abs blockIdx*64).
        for (int i = tid; i < 1024; i += NT) {
            int py = i >> 5, px = i & 31;
            const float* p = dst + (2 * py) * BD + 2 * px;
            float m = fmaxf(fmaxf(p[0], p[1]), fmaxf(p[BD], p[BD + 1]));
            out[(long)(oy + py) * outW + ox + px] = m;
        }
    }
}

extern "C" void kernel_launch(void* const* d_in, const int* in_sizes, int n_in,
                              void* d_out, int out_size) {
    const float* x = (const float*)d_in[0];
    const float* w[10];
    for (int i = 0; i < 10; ++i) w[i] = (const float*)d_in[1 + i];

    float *b0, *b1, *b2;
    cudaGetSymbolAddress((void**)&b0, g_buf0);
    cudaGetSymbolAddress((void**)&b1, g_buf1);
    cudaGetSymbolAddress((void**)&b2, g_buf2);

    float* outp = (float*)d_out;

    stage_kernel<2><<<dim3(128, 128), NT>>>(x,  8192, b0,  4096, w[0], w[1], nullptr);
    stage_kernel<2><<<dim3(64, 64),   NT>>>(b0, 4096, b1,  2048, w[2], w[3], nullptr);
    stage_kernel<3><<<dim3(32, 32),   NT>>>(b1, 2048, b2,  1024, w[4], w[5], w[6]);
    stage_kernel<3><<<dim3(16, 16),   NT>>>(b2, 1024, outp, 512, w[7], w[8], w[9]);
}